// round 4
// baseline (speedup 1.0000x reference)
#include <cuda_runtime.h>

// Caps_Layer: B=128, N=512, D=300, NC=10, DC=64, ROUTINGS=5
// Multi-kernel pipeline (graph-capturable, no allocs):
//   k_init:  s[b,d] = 0.1 * sum_j x[b,j,d]
//   k_bc m0: y:=s (uniform over i) -> o (P2+squash) -> v (P3)
//   repeat r=1..4: k_xpass (b=x*v, softmax, y=c*x) ; k_bc (m1, or m2 last: write out)
// k_bc caches W_i[300x64] in smem: W read once per (i, 8-batch group) -> 15x less L2.

#define NN 512
#define DD 300
#define NC 10
#define DC 64
#define MM 640
#define BB 128

typedef unsigned long long u64;
struct u64x2_t { u64 x, y; };

__device__ float y_g[BB * NC * DD];
__device__ float v_g[BB * NC * DD];
__device__ float s_g[BB * DD];

__device__ __forceinline__ void fma2(u64& acc, u64 a, u64 b) {
    asm("fma.rn.f32x2 %0, %1, %2, %0;" : "+l"(acc) : "l"(a), "l"(b));
}
__device__ __forceinline__ u64 splat2(float f) {
    u64 r; asm("mov.b64 %0, {%1,%1};" : "=l"(r) : "f"(f)); return r;
}
__device__ __forceinline__ float fold2(u64 v) {
    float lo, hi; asm("mov.b64 {%0,%1}, %2;" : "=f"(lo), "=f"(hi) : "l"(v)); return lo + hi;
}
__device__ __forceinline__ void cp16(void* smem_dst, const void* gsrc) {
    unsigned sa = (unsigned)__cvta_generic_to_shared(smem_dst);
    asm volatile("cp.async.cg.shared.global [%0], [%1], 16;" :: "r"(sa), "l"(gsrc));
}
__device__ __forceinline__ void cp_commit() { asm volatile("cp.async.commit_group;"); }
template <int N> __device__ __forceinline__ void cp_wait() {
    asm volatile("cp.async.wait_group %0;" :: "n"(N));
}

// ======================= k_init =======================
__global__ __launch_bounds__(640, 1) void k_init(const float* __restrict__ x)
{
    __shared__ float p[600];
    const int b = blockIdx.x, t = threadIdx.x;
    const float* __restrict__ xb = x + (size_t)b * NN * DD;
    if (t < 600) {
        const int g = t / 300, d = t - g * 300;
        const float* __restrict__ xp = xb + (size_t)(g * 256) * DD + d;
        float a0 = 0.f, a1 = 0.f, a2 = 0.f, a3 = 0.f;
        for (int j = 0; j < 256; j += 4) {
            a0 += xp[(j + 0) * DD]; a1 += xp[(j + 1) * DD];
            a2 += xp[(j + 2) * DD]; a3 += xp[(j + 3) * DD];
        }
        p[g * 300 + d] = (a0 + a1) + (a2 + a3);
    }
    __syncthreads();
    if (t < 300) s_g[b * DD + t] = 0.1f * (p[t] + p[300 + t]);
}

// ======================= k_bc =======================
// grid = 10 i * 16 bgroups = 160 CTAs, 256 threads (8 warps), 8 batches per CTA.
// smem: W_s[300][68] pad, y_s[8][300], opart[8][512], o_s[512], v_s[8][300], nrm[8]
#define BC_WS   0
#define BC_YS   20400
#define BC_OP   22800
#define BC_OS   26896
#define BC_VS   27408
#define BC_NRM  29808
#define BC_FL   29816
#define BC_BYTES (BC_FL * 4)

__global__ __launch_bounds__(256, 1) void k_bc(const float* __restrict__ W,
                                               float* __restrict__ out, int mode)
{
    extern __shared__ float sm[];
    float* W_s   = sm + BC_WS;
    float* y_s   = sm + BC_YS;
    float* opart = sm + BC_OP;
    float* o_s   = sm + BC_OS;
    float* v_s   = sm + BC_VS;
    float* nrm   = sm + BC_NRM;

    const int t = threadIdx.x, w = t >> 5, lane = t & 31;
    const int blk = blockIdx.x, i = blk % 10, bg = blk / 10, b0 = bg * 8;

    for (int idx = t; idx < 300 * 16; idx += 256) {
        const int row = idx >> 4, c4 = idx & 15;
        cp16(W_s + row * 68 + c4 * 4, W + (size_t)row * MM + i * DC + c4 * 4);
    }
    for (int idx = t; idx < 600; idx += 256) {
        const int row = idx / 75, c = idx - row * 75;
        const float* src = (mode == 0)
            ? (s_g + (size_t)(b0 + row) * DD + c * 4)
            : (y_g + (size_t)(b0 + row) * (NC * DD) + i * DD + c * 4);
        cp16(y_s + row * 300 + c * 4, src);
    }
    cp_commit(); cp_wait<0>(); __syncthreads();

    // P2: o[b,k] = sum_d y[b,d] W_s[d,k]  (warp = d-chunk, lane = 2k, b in regs)
    {
        const int d0  = (w < 4) ? w * 38 : 152 + (w - 4) * 37;
        const int len = (w < 4) ? 38 : 37;
        const int k0 = lane * 2;
        u64 acc[8];
        #pragma unroll
        for (int b = 0; b < 8; ++b) acc[b] = 0ull;
        for (int dd = 0; dd < len; ++dd) {
            const int d = d0 + dd;
            const u64 wv = *(const u64*)(W_s + d * 68 + k0);
            #pragma unroll
            for (int b = 0; b < 8; ++b) fma2(acc[b], wv, splat2(y_s[b * 300 + d]));
        }
        #pragma unroll
        for (int b = 0; b < 8; ++b) *(u64*)(opart + w * 512 + b * 64 + k0) = acc[b];
    }
    __syncthreads();
    // reduce partial o over 8 warps
    #pragma unroll
    for (int rep = 0; rep < 2; ++rep) {
        const int idx = rep * 256 + t;
        float o = 0.f;
        #pragma unroll
        for (int ww = 0; ww < 8; ++ww) o += opart[ww * 512 + idx];
        o_s[idx] = o;
    }
    __syncthreads();
    // squash norms: warp = b
    {
        const float a = o_s[w * 64 + lane], c = o_s[w * 64 + 32 + lane];
        float s = a * a + c * c;
        #pragma unroll
        for (int k = 16; k > 0; k >>= 1) s += __shfl_xor_sync(0xffffffffu, s, k);
        if (lane == 0) nrm[w] = rsqrtf(s + 1e-7f);
    }
    __syncthreads();
    #pragma unroll
    for (int rep = 0; rep < 2; ++rep) {
        const int idx = rep * 256 + t, b = idx >> 6, k = idx & 63;
        const float o = o_s[idx] * nrm[b];
        o_s[idx] = o;
        if (mode == 2) out[(size_t)(b0 + b) * MM + i * DC + k] = o;
    }
    if (mode == 2) return;
    __syncthreads();

    // P3: v[b,d] = sum_k o[b,k] W_s[d,k]  (warp = d-chunk, lane = d)
    {
        const int d0  = (w < 4) ? w * 38 : 152 + (w - 4) * 37;
        const int len = (w < 4) ? 38 : 37;
        #pragma unroll
        for (int pass = 0; pass < 2; ++pass) {
            const int dd = pass * 32 + lane;
            if (dd < len) {
                const int d = d0 + dd;
                u64 acc[8];
                #pragma unroll
                for (int b = 0; b < 8; ++b) acc[b] = 0ull;
                #pragma unroll
                for (int k4 = 0; k4 < 16; ++k4) {
                    const u64x2_t wv = *(const u64x2_t*)(W_s + d * 68 + k4 * 4);
                    #pragma unroll
                    for (int b = 0; b < 8; ++b) {
                        const u64x2_t ov = *(const u64x2_t*)(o_s + b * 64 + k4 * 4);
                        fma2(acc[b], wv.x, ov.x); fma2(acc[b], wv.y, ov.y);
                    }
                }
                #pragma unroll
                for (int b = 0; b < 8; ++b) v_s[b * 300 + d] = fold2(acc[b]);
            }
        }
    }
    __syncthreads();
    for (int idx = t; idx < 600; idx += 256) {
        const int row = idx / 75, c = idx - row * 75;
        *(float4*)(v_g + (size_t)(b0 + row) * (NC * DD) + i * DD + c * 4) =
            *(const float4*)(v_s + row * 300 + c * 4);
    }
}

// ======================= k_xpass =======================
// grid 128, 640 threads. Tiles of 32 j, double-buffered cp.async, rows padded to 304.
#define XPAD 304
#define AR_BUF (32 * XPAD)     // 9728
#define A_AR   0
#define A_V    19456           // 3000
#define A_YP   22456           // 12000
#define A_BP   34456           // 7040  (20 warps * 352)
#define A_C2   41496           // 640 floats = 320 u64
#define A_FL   42136
#define A_BYTES (A_FL * 4)

__global__ __launch_bounds__(640, 1) void k_xpass(const float* __restrict__ x)
{
    extern __shared__ float sm[];
    const int b = blockIdx.x, t = threadIdx.x, w = t >> 5, lane = t & 31;
    const float* __restrict__ xb = x + (size_t)b * NN * DD;
    float* v_s = sm + A_V;
    float* yp  = sm + A_YP;
    float* bp  = sm + A_BP;
    u64*   c2  = (u64*)(sm + A_C2);

    // v load + tile-0 prefetch (one group)
    for (int idx = t; idx < 750; idx += 640)
        cp16(v_s + idx * 4, v_g + (size_t)b * 3000 + idx * 4);
    for (int idx = t; idx < 2400; idx += 640) {
        const int row = idx / 75, c = idx - row * 75;
        cp16(sm + A_AR + row * XPAD + c * 4, xb + (size_t)row * DD + c * 4);
    }
    cp_commit();

    u64 yacc[NC];
    #pragma unroll
    for (int i = 0; i < NC; ++i) yacc[i] = 0ull;
    const int jg = t / 150, dp = t - jg * 150, d0c = dp * 2;   // valid for t<600

    // B-phase d-chunks: 15 warps x 16d + 5 warps x 12d = 300 (all multiples of 4)
    const int dB0 = (w < 15) ? w * 16 : 240 + (w - 15) * 12;
    const int nB  = (w < 15) ? 4 : 3;          // u64x2 count

    for (int tile = 0; tile < 16; ++tile) {
        if (tile < 15) {
            const int nb = (tile + 1) & 1;
            const float* gs = xb + (size_t)(tile + 1) * 32 * DD;
            for (int idx = t; idx < 2400; idx += 640) {
                const int row = idx / 75, c = idx - row * 75;
                cp16(sm + A_AR + nb * AR_BUF + row * XPAD + c * 4,
                     gs + (size_t)row * DD + c * 4);
            }
            cp_commit(); cp_wait<1>();
        } else {
            cp_wait<0>();
        }
        __syncthreads();
        const float* xs = sm + A_AR + (tile & 1) * AR_BUF;

        // ---- B: b[i, j=lane] partials over this warp's d-chunk ----
        {
            u64 acc[NC];
            #pragma unroll
            for (int i = 0; i < NC; ++i) acc[i] = 0ull;
            u64x2_t xv[4];
            #pragma unroll
            for (int p = 0; p < 4; ++p)
                if (p < nB) xv[p] = *(const u64x2_t*)(xs + lane * XPAD + dB0 + p * 4);
            #pragma unroll
            for (int i = 0; i < NC; ++i) {
                const float* vb = v_s + i * DD + dB0;
                #pragma unroll
                for (int p = 0; p < 4; ++p) {
                    if (p < nB) {
                        const u64x2_t vv = *(const u64x2_t*)(vb + p * 4);
                        fma2(acc[i], xv[p].x, vv.x);
                        fma2(acc[i], xv[p].y, vv.y);
                    }
                }
            }
            #pragma unroll
            for (int i = 0; i < NC; ++i) bp[w * 352 + lane * 11 + i] = fold2(acc[i]);
        }
        __syncthreads();

        // ---- softmax over i per j; store pre-splatted c ----
        if (t < 512) {
            const int j = t >> 4, ii = t & 15;
            float s;
            if (ii < NC) {
                s = 0.f;
                #pragma unroll
                for (int ww = 0; ww < 20; ++ww) s += bp[ww * 352 + j * 11 + ii];
            } else s = -1e30f;
            float m = s;
            #pragma unroll
            for (int k = 8; k > 0; k >>= 1)
                m = fmaxf(m, __shfl_xor_sync(0xffffffffu, m, k, 16));
            const float e = __expf(s - m);
            float su = e;
            #pragma unroll
            for (int k = 8; k > 0; k >>= 1)
                su += __shfl_xor_sync(0xffffffffu, su, k, 16);
            if (ii < NC) c2[j * NC + ii] = splat2(e * (1.0f / su));
        }
        __syncthreads();

        // ---- C: yacc[i] += c[i,j] * x[j, d0c..d0c+1] ----
        if (t < 600) {
            const int j0 = jg * 8;
            #pragma unroll
            for (int jj = 0; jj < 8; ++jj) {
                const int j = j0 + jj;
                const u64 xv = *(const u64*)(xs + j * XPAD + d0c);
                #pragma unroll
                for (int p = 0; p < 5; ++p) {
                    const u64x2_t cc = *(const u64x2_t*)(&c2[j * NC + 2 * p]);
                    fma2(yacc[2 * p],     xv, cc.x);
                    fma2(yacc[2 * p + 1], xv, cc.y);
                }
            }
        }
        __syncthreads();
    }

    if (t < 600) {
        #pragma unroll
        for (int i = 0; i < NC; ++i)
            *(u64*)(yp + jg * 3000 + i * DD + d0c) = yacc[i];
    }
    __syncthreads();
    for (int idx = t; idx < 3000; idx += 640)
        y_g[(size_t)b * 3000 + idx] =
            (yp[idx] + yp[3000 + idx]) + (yp[6000 + idx] + yp[9000 + idx]);
}

// ======================= launch =======================
extern "C" void kernel_launch(void* const* d_in, const int* in_sizes, int n_in,
                              void* d_out, int out_size)
{
    const float* x = (const float*)d_in[0];
    const float* W = (const float*)d_in[1];
    if (n_in >= 2 && in_sizes[0] < in_sizes[1]) {
        x = (const float*)d_in[1];
        W = (const float*)d_in[0];
    }
    float* out = (float*)d_out;

    static int attr_done = 0;
    if (!attr_done) {
        cudaFuncSetAttribute(k_bc,    cudaFuncAttributeMaxDynamicSharedMemorySize, BC_BYTES);
        cudaFuncSetAttribute(k_xpass, cudaFuncAttributeMaxDynamicSharedMemorySize, A_BYTES);
        attr_done = 1;
    }

    k_init<<<BB, 640>>>(x);
    k_bc<<<160, 256, BC_BYTES>>>(W, out, 0);
    for (int r = 1; r <= 4; ++r) {
        k_xpass<<<BB, 640, A_BYTES>>>(x);
        k_bc<<<160, 256, BC_BYTES>>>(W, out, (r == 4) ? 2 : 1);
    }
}

// round 5
// speedup vs baseline: 1.2537x; 1.2537x over previous
#include <cuda_runtime.h>

// Caps_Layer: B=128, N=512, D=300, NC=10, DC=64, ROUTINGS=5
// Pipeline: k_init; k_bc(m0); 4x[ k_xpass ; k_bc(m1|m2) ]
// k_bc: grid 320 = (10 i x 32 bgroups), 4 batches/CTA, W_i[300x64] cached in smem
//       -> W chip traffic ~25MB/call vs ~200MB fused.  (R4 spill fixed: 4-batch blocking)
// k_xpass: grid 128, 640 thr, R3's proven conflict-free stride-300 tile layout.

#define NN 512
#define DD 300
#define NC 10
#define DC 64
#define MM 640
#define BB 128

typedef unsigned long long u64;
struct u64x2_t { u64 x, y; };

__device__ float y_g[BB * NC * DD];
__device__ float v_g[BB * NC * DD];
__device__ float s_g[BB * DD];

__device__ __forceinline__ void fma2(u64& acc, u64 a, u64 b) {
    asm("fma.rn.f32x2 %0, %1, %2, %0;" : "+l"(acc) : "l"(a), "l"(b));
}
__device__ __forceinline__ u64 splat2(float f) {
    u64 r; asm("mov.b64 %0, {%1,%1};" : "=l"(r) : "f"(f)); return r;
}
__device__ __forceinline__ float fold2(u64 v) {
    float lo, hi; asm("mov.b64 {%0,%1}, %2;" : "=f"(lo), "=f"(hi) : "l"(v)); return lo + hi;
}
__device__ __forceinline__ void cp16(void* smem_dst, const void* gsrc) {
    unsigned sa = (unsigned)__cvta_generic_to_shared(smem_dst);
    asm volatile("cp.async.cg.shared.global [%0], [%1], 16;" :: "r"(sa), "l"(gsrc));
}
__device__ __forceinline__ void cp_commit() { asm volatile("cp.async.commit_group;"); }
template <int N> __device__ __forceinline__ void cp_wait() {
    asm volatile("cp.async.wait_group %0;" :: "n"(N));
}

// ======================= k_init: s[b,d] = 0.1 * colsum(x) =======================
__global__ __launch_bounds__(640, 1) void k_init(const float* __restrict__ x)
{
    __shared__ float p[600];
    const int b = blockIdx.x, t = threadIdx.x;
    const float* __restrict__ xb = x + (size_t)b * NN * DD;
    if (t < 600) {
        const int g = t / 300, d = t - g * 300;
        const float* __restrict__ xp = xb + (size_t)(g * 256) * DD + d;
        float a0 = 0.f, a1 = 0.f, a2 = 0.f, a3 = 0.f;
        for (int j = 0; j < 256; j += 4) {
            a0 += xp[(j + 0) * DD]; a1 += xp[(j + 1) * DD];
            a2 += xp[(j + 2) * DD]; a3 += xp[(j + 3) * DD];
        }
        p[g * 300 + d] = (a0 + a1) + (a2 + a3);
    }
    __syncthreads();
    if (t < 300) s_g[b * DD + t] = 0.1f * (p[t] + p[300 + t]);
}

// ======================= k_bc =======================
// grid = 10 i * 32 bgroups = 320 CTAs, 256 threads, 4 batches per CTA.
#define BC_WS   0        // 300*68 = 20400
#define BC_YS   20400    // 4*300  = 1200
#define BC_OP   21600    // 8*256  = 2048
#define BC_OS   23648    // 256
#define BC_VS   23904    // 4*300  = 1200
#define BC_NRM  25104    // 8
#define BC_FL   25112
#define BC_BYTES (BC_FL * 4)

__global__ __launch_bounds__(256, 2) void k_bc(const float* __restrict__ W,
                                               float* __restrict__ out, int mode)
{
    extern __shared__ float sm[];
    float* W_s   = sm + BC_WS;
    float* y_s   = sm + BC_YS;
    float* opart = sm + BC_OP;
    float* o_s   = sm + BC_OS;
    float* v_s   = sm + BC_VS;
    float* nrm   = sm + BC_NRM;

    const int t = threadIdx.x, w = t >> 5, lane = t & 31;
    const int blk = blockIdx.x, i = blk % 10, bg = blk / 10, b0 = bg * 4;

    // stage W_i [300 x 64] (rows padded to 68 floats: 17 quads, odd -> conflict-free)
    for (int idx = t; idx < 300 * 16; idx += 256) {
        const int row = idx >> 4, c4 = idx & 15;
        cp16(W_s + row * 68 + c4 * 4, W + (size_t)row * MM + i * DC + c4 * 4);
    }
    // stage y (or s for mode 0): 4 batches x 300
    for (int idx = t; idx < 300; idx += 256) {
        const int row = idx / 75, c = idx - row * 75;
        const float* src = (mode == 0)
            ? (s_g + (size_t)(b0 + row) * DD + c * 4)
            : (y_g + (size_t)(b0 + row) * (NC * DD) + i * DD + c * 4);
        cp16(y_s + row * 300 + c * 4, src);
    }
    cp_commit(); cp_wait<0>(); __syncthreads();

    // P2: o[b,k] = sum_d y[b,d] W_s[d,k]   (warp = d-chunk, lane = 2k, 4 b in regs)
    {
        const int d0  = w * 38;
        const int len = (w == 7) ? 34 : 38;
        const int k0  = lane * 2;
        u64 acc[4];
        #pragma unroll
        for (int bb = 0; bb < 4; ++bb) acc[bb] = 0ull;
        for (int dd = 0; dd < len; ++dd) {
            const int d = d0 + dd;
            const u64 wv = *(const u64*)(W_s + d * 68 + k0);
            #pragma unroll
            for (int bb = 0; bb < 4; ++bb) fma2(acc[bb], wv, splat2(y_s[bb * 300 + d]));
        }
        #pragma unroll
        for (int bb = 0; bb < 4; ++bb) *(u64*)(opart + w * 256 + bb * 64 + k0) = acc[bb];
    }
    __syncthreads();
    // reduce partial o over 8 warps
    {
        float o = 0.f;
        #pragma unroll
        for (int ww = 0; ww < 8; ++ww) o += opart[ww * 256 + t];
        o_s[t] = o;
    }
    __syncthreads();
    // squash norms: warps 0-3 = batches
    if (w < 4) {
        const float a = o_s[w * 64 + lane], c = o_s[w * 64 + 32 + lane];
        float s = a * a + c * c;
        #pragma unroll
        for (int k = 16; k > 0; k >>= 1) s += __shfl_xor_sync(0xffffffffu, s, k);
        if (lane == 0) nrm[w] = rsqrtf(s + 1e-7f);
    }
    __syncthreads();
    {
        const int bb = t >> 6, k = t & 63;
        const float o = o_s[t] * nrm[bb];
        o_s[t] = o;
        if (mode == 2) out[(size_t)(b0 + bb) * MM + i * DC + k] = o;
    }
    if (mode == 2) return;
    __syncthreads();

    // P3: v[b,d] = sum_k o[b,k] W_s[d,k]  (warp = d-chunk, lanes = d)
    {
        const int d0  = w * 38;
        const int len = (w == 7) ? 34 : 38;
        #pragma unroll
        for (int pass = 0; pass < 2; ++pass) {
            const int dd = pass * 32 + lane;
            if (dd < len) {
                const int d = d0 + dd;
                u64 acc[4];
                #pragma unroll
                for (int bb = 0; bb < 4; ++bb) acc[bb] = 0ull;
                #pragma unroll
                for (int k4 = 0; k4 < 16; ++k4) {
                    const u64x2_t wv = *(const u64x2_t*)(W_s + d * 68 + k4 * 4);
                    #pragma unroll
                    for (int bb = 0; bb < 4; ++bb) {
                        const u64x2_t ov = *(const u64x2_t*)(o_s + bb * 64 + k4 * 4);
                        fma2(acc[bb], wv.x, ov.x); fma2(acc[bb], wv.y, ov.y);
                    }
                }
                #pragma unroll
                for (int bb = 0; bb < 4; ++bb) v_s[bb * 300 + d] = fold2(acc[bb]);
            }
        }
    }
    __syncthreads();
    for (int idx = t; idx < 300; idx += 256) {
        const int row = idx / 75, c = idx - row * 75;
        *(float4*)(v_g + (size_t)(b0 + row) * (NC * DD) + i * DD + c * 4) =
            *(const float4*)(v_s + row * 300 + c * 4);
    }
}

// ======================= k_xpass (R3 layout: stride-300, conflict-free) =======================
#define AR_BUF (32 * DD)       // 9600 floats per tile buffer
#define A_AR   0               // 2 buffers: 19200
#define A_V    19200           // 3000
#define A_YP   22200           // 12000
#define A_BP   34200           // 7040  (20 warps * 352)
#define A_C2   41240           // 640 floats = 320 u64
#define A_FL   41880
#define A_BYTES (A_FL * 4)

__global__ __launch_bounds__(640, 1) void k_xpass(const float* __restrict__ x)
{
    extern __shared__ float sm[];
    const int b = blockIdx.x, t = threadIdx.x, w = t >> 5, lane = t & 31;
    const float* __restrict__ xb = x + (size_t)b * NN * DD;
    float* v_s = sm + A_V;
    float* yp  = sm + A_YP;
    float* bp  = sm + A_BP;
    u64*   c2  = (u64*)(sm + A_C2);

    // v load + tile-0 prefetch (one cp group)
    for (int idx = t; idx < 750; idx += 640)
        cp16(v_s + idx * 4, v_g + (size_t)b * 3000 + idx * 4);
    for (int idx = t; idx < 2400; idx += 640)
        cp16(sm + A_AR + idx * 4, xb + idx * 4);
    cp_commit();

    u64 yacc[NC];
    #pragma unroll
    for (int i = 0; i < NC; ++i) yacc[i] = 0ull;
    const int jg = t / 150, dp = t - jg * 150, d0c = dp * 2;   // valid for t<600

    // B-phase d-chunks: 15 warps x 16d + 5 warps x 12d
    const int dB0 = (w < 15) ? w * 16 : 240 + (w - 15) * 12;
    const int nB  = (w < 15) ? 4 : 3;

    for (int tile = 0; tile < 16; ++tile) {
        if (tile < 15) {
            const int nb = (tile + 1) & 1;
            const float* gs = xb + (size_t)(tile + 1) * 32 * DD;
            for (int idx = t; idx < 2400; idx += 640)
                cp16(sm + A_AR + nb * AR_BUF + idx * 4, gs + idx * 4);
            cp_commit(); cp_wait<1>();
        } else {
            cp_wait<0>();
        }
        __syncthreads();
        const float* xs = sm + A_AR + (tile & 1) * AR_BUF;

        // ---- B: b[i, j=lane] partials over this warp's d-chunk ----
        {
            u64 acc[NC];
            #pragma unroll
            for (int i = 0; i < NC; ++i) acc[i] = 0ull;
            u64x2_t xv[4];
            #pragma unroll
            for (int p = 0; p < 4; ++p)
                if (p < nB) xv[p] = *(const u64x2_t*)(xs + lane * DD + dB0 + p * 4);
            #pragma unroll
            for (int i = 0; i < NC; ++i) {
                const float* vb = v_s + i * DD + dB0;
                #pragma unroll
                for (int p = 0; p < 4; ++p) {
                    if (p < nB) {
                        const u64x2_t vv = *(const u64x2_t*)(vb + p * 4);
                        fma2(acc[i], xv[p].x, vv.x);
                        fma2(acc[i], xv[p].y, vv.y);
                    }
                }
            }
            #pragma unroll
            for (int i = 0; i < NC; ++i) bp[w * 352 + lane * 11 + i] = fold2(acc[i]);
        }
        __syncthreads();

        // ---- softmax over i per j ----
        if (t < 512) {
            const int j = t >> 4, ii = t & 15;
            float s;
            if (ii < NC) {
                s = 0.f;
                #pragma unroll
                for (int ww = 0; ww < 20; ++ww) s += bp[ww * 352 + j * 11 + ii];
            } else s = -1e30f;
            float m = s;
            #pragma unroll
            for (int k = 8; k > 0; k >>= 1)
                m = fmaxf(m, __shfl_xor_sync(0xffffffffu, m, k, 16));
            const float e = __expf(s - m);
            float su = e;
            #pragma unroll
            for (int k = 8; k > 0; k >>= 1)
                su += __shfl_xor_sync(0xffffffffu, su, k, 16);
            if (ii < NC) c2[j * NC + ii] = splat2(e * (1.0f / su));
        }
        __syncthreads();

        // ---- C: yacc[i] += c[i,j] * x[j, d0c..d0c+1] ----
        if (t < 600) {
            const int j0 = jg * 8;
            #pragma unroll
            for (int jj = 0; jj < 8; ++jj) {
                const int j = j0 + jj;
                const u64 xv = *(const u64*)(xs + j * DD + d0c);
                #pragma unroll
                for (int p = 0; p < 5; ++p) {
                    const u64x2_t cc = *(const u64x2_t*)(&c2[j * NC + 2 * p]);
                    fma2(yacc[2 * p],     xv, cc.x);
                    fma2(yacc[2 * p + 1], xv, cc.y);
                }
            }
        }
        __syncthreads();
    }

    if (t < 600) {
        #pragma unroll
        for (int i = 0; i < NC; ++i)
            *(u64*)(yp + jg * 3000 + i * DD + d0c) = yacc[i];
    }
    __syncthreads();
    for (int idx = t; idx < 3000; idx += 640)
        y_g[(size_t)b * 3000 + idx] =
            (yp[idx] + yp[3000 + idx]) + (yp[6000 + idx] + yp[9000 + idx]);
}

// ======================= launch =======================
extern "C" void kernel_launch(void* const* d_in, const int* in_sizes, int n_in,
                              void* d_out, int out_size)
{
    const float* x = (const float*)d_in[0];
    const float* W = (const float*)d_in[1];
    if (n_in >= 2 && in_sizes[0] < in_sizes[1]) {
        x = (const float*)d_in[1];
        W = (const float*)d_in[0];
    }
    float* out = (float*)d_out;

    static int attr_done = 0;
    if (!attr_done) {
        cudaFuncSetAttribute(k_bc,    cudaFuncAttributeMaxDynamicSharedMemorySize, BC_BYTES);
        cudaFuncSetAttribute(k_xpass, cudaFuncAttributeMaxDynamicSharedMemorySize, A_BYTES);
        attr_done = 1;
    }

    k_init<<<BB, 640>>>(x);
    k_bc<<<320, 256, BC_BYTES>>>(W, out, 0);
    for (int r = 1; r <= 4; ++r) {
        k_xpass<<<BB, 640, A_BYTES>>>(x);
        k_bc<<<320, 256, BC_BYTES>>>(W, out, (r == 4) ? 2 : 1);
    }
}

// round 6
// speedup vs baseline: 1.3390x; 1.0681x over previous
#include <cuda_runtime.h>

// Caps_Layer: B=128, N=512, D=300, NC=10, DC=64, ROUTINGS=5  (fused, 1 CTA/batch)
// u = x@W never materialized. Per iteration:
//   P2: o_raw[m] = sum_d y[i,d] W[d,m] ; squash -> o
//   P3: v[i,d] = sum_k o[i,k] Wt[i*64+k, d]   (pre-transposed W)
//   XPASS tiled over j (64/tile, double-buffered cp.async):
//       b = x*v (20 warps: 2 j-halves x 10 d-chunks), softmax (1 phase, both halves),
//       y += c*x (register accumulators, flushed once; yp overlaid on arena buf0)
// Iteration 0: c uniform -> y = 0.1*colsum(x).

#define NN 512
#define DD 300
#define NC 10
#define DC 64
#define MM 640
#define BB 128
#define NT 640
#define TJ 64
#define NTILE 8
#define AR_BUF (TJ * DD)        // 19200 floats per buffer

#define OFF_AR  0               // 2 buffers = 38400 (yp[12000] overlays buf0)
#define OFF_V   38400           // 3000
#define OFF_Y   41400           // 3000
#define OFF_BP  44400           // 7040 (20 warps * 352)  (also P2 partials / it0 scratch)
#define OFF_C2  51440           // 1280 floats = 640 u64 (64 j * 10 i splatted c)
#define OFF_O   52720           // 640
#define OFF_NRM 53360           // 16
#define SMEM_FLOATS 53376
#define SMEM_BYTES (SMEM_FLOATS * 4)

typedef unsigned long long u64;
struct u64x2_t { u64 x, y; };

__device__ float Wt_g[MM * DD];   // W transposed: Wt[m*300 + d]

__device__ __forceinline__ void fma2(u64& acc, u64 a, u64 b) {
    asm("fma.rn.f32x2 %0, %1, %2, %0;" : "+l"(acc) : "l"(a), "l"(b));
}
__device__ __forceinline__ u64 splat2(float f) {
    u64 r; asm("mov.b64 %0, {%1,%1};" : "=l"(r) : "f"(f)); return r;
}
__device__ __forceinline__ float fold2(u64 v) {
    float lo, hi; asm("mov.b64 {%0,%1}, %2;" : "=f"(lo), "=f"(hi) : "l"(v)); return lo + hi;
}
__device__ __forceinline__ void cp16(void* smem_dst, const void* gsrc) {
    unsigned sa = (unsigned)__cvta_generic_to_shared(smem_dst);
    asm volatile("cp.async.cg.shared.global [%0], [%1], 16;" :: "r"(sa), "l"(gsrc));
}
__device__ __forceinline__ void cp_commit() { asm volatile("cp.async.commit_group;"); }
template <int N> __device__ __forceinline__ void cp_wait() {
    asm volatile("cp.async.wait_group %0;" :: "n"(N));
}

// ---------------- prologue: W[300][640] -> Wt[640][300] ----------------
__global__ void transpose_W(const float* __restrict__ W)
{
    __shared__ float tl[32][33];
    const int tx = threadIdx.x, ty = threadIdx.y;     // 32 x 8
    const int m0 = blockIdx.x * 32, d0 = blockIdx.y * 32;
    #pragma unroll
    for (int k = 0; k < 4; ++k) {
        const int d = d0 + ty + k * 8;
        if (d < DD) tl[ty + k * 8][tx] = W[(size_t)d * MM + m0 + tx];
    }
    __syncthreads();
    #pragma unroll
    for (int k = 0; k < 4; ++k) {
        const int m = m0 + ty + k * 8;
        const int d = d0 + tx;
        if (d < DD) Wt_g[(size_t)m * DD + d] = tl[tx][ty + k * 8];
    }
}

__global__ __launch_bounds__(NT, 1)
void caps_kernel(const float* __restrict__ x,
                 const float* __restrict__ W,
                 float* __restrict__ out)
{
    extern __shared__ float sm[];
    const int b    = blockIdx.x;
    const int t    = threadIdx.x;
    const int w    = t >> 5;
    const int lane = t & 31;
    const float* __restrict__ xb = x + (size_t)b * NN * DD;

    float* v_s  = sm + OFF_V;
    float* y_s  = sm + OFF_Y;
    float* bp   = sm + OFF_BP;
    u64*   c2   = (u64*)(sm + OFF_C2);
    float* o_s  = sm + OFF_O;
    float* nrm  = sm + OFF_NRM;
    float* yp   = sm + OFF_AR;         // overlay (buf0), valid only at flush time

    // ---- iteration 0: y[i,d] = 0.1 * colsum_d(x) ----
    if (t < 600) {
        const int g = t / 300, d = t - g * 300;
        const float* __restrict__ xp = xb + (size_t)(g * 256) * DD + d;
        float a0 = 0.f, a1 = 0.f, a2 = 0.f, a3 = 0.f;
        for (int j = 0; j < 256; j += 4) {
            a0 += xp[(j + 0) * DD]; a1 += xp[(j + 1) * DD];
            a2 += xp[(j + 2) * DD]; a3 += xp[(j + 3) * DD];
        }
        bp[g * 300 + d] = (a0 + a1) + (a2 + a3);
    }
    __syncthreads();
    for (int idx = t; idx < NC * DD; idx += NT) {
        const int d = idx % DD;
        y_s[idx] = 0.1f * (bp[d] + bp[300 + d]);
    }
    __syncthreads();

    for (int r = 0; r < 5; ++r) {
        // ---- early prefetch of XPASS tile 0 (hides x latency under P2/P3) ----
        if (r < 4) {
            for (int idx = t; idx < AR_BUF / 4; idx += NT)
                cp16(sm + OFF_AR + idx * 4, xb + idx * 4);
            cp_commit();
        }

        // ---------------- P2: o_raw[m] = sum_d y[i,d] W[d,m] ----------------
        {
            const int ds  = t / 160;            // d-slice 0..3
            const int m4  = (t - ds * 160) * 4; // 4 consecutive m
            const int ci  = m4 >> 6;
            const int d0  = ds * 75;
            const float* __restrict__ ypt = y_s + ci * DD;
            u64 a01 = 0ull, a23 = 0ull;
            #pragma unroll 5
            for (int d = d0; d < d0 + 75; ++d) {
                const u64x2_t w4 = *(const u64x2_t*)(W + (size_t)d * MM + m4);
                const u64 ys = splat2(ypt[d]);
                fma2(a01, w4.x, ys); fma2(a23, w4.y, ys);
            }
            *(u64*)(bp + ds * MM + m4)     = a01;
            *(u64*)(bp + ds * MM + m4 + 2) = a23;
        }
        __syncthreads();
        o_s[t] = bp[t] + bp[MM + t] + bp[2 * MM + t] + bp[3 * MM + t];
        __syncthreads();
        if (t < 320) {   // squash norms: 10 warps, shuffle reduce
            const int i = t >> 5;
            const float v0 = o_s[i * DC + lane];
            const float v1 = o_s[i * DC + 32 + lane];
            float s = v0 * v0 + v1 * v1;
            #pragma unroll
            for (int k = 16; k > 0; k >>= 1) s += __shfl_xor_sync(0xffffffffu, s, k);
            if (lane == 0) nrm[i] = rsqrtf(s + 1e-7f);
        }
        __syncthreads();
        const float ov = o_s[t] * nrm[t >> 6];
        o_s[t] = ov;
        if (r == 4) { out[(size_t)b * MM + t] = ov; break; }
        __syncthreads();

        // ---------------- P3: v[i,d] = sum_k o[i,k] Wt[i*64+k, d] ----------------
        for (int idx = t; idx < NC * 150; idx += NT) {
            const int i  = idx / 150;
            const int d0 = (idx - i * 150) * 2;
            const float* __restrict__ ob = o_s + i * DC;
            const float* __restrict__ wt = Wt_g + (size_t)i * DC * DD + d0;
            u64 acc = 0ull;
            #pragma unroll 8
            for (int k = 0; k < DC; ++k)
                fma2(acc, *(const u64*)(wt + (size_t)k * DD), splat2(ob[k]));
            *(u64*)(v_s + i * DD + d0) = acc;
        }
        __syncthreads();

        // ---------------- XPASS ----------------
        u64 yacc[NC];
        #pragma unroll
        for (int i = 0; i < NC; ++i) yacc[i] = 0ull;
        const int jg  = t / 150;
        const int d0c = (t - jg * 150) * 2;     // valid for t<600

        // B-phase mapping: warps 0-9 -> j-half 0 (d-chunks of 30), warps 10-19 -> half 1
        const int wj = (w < 10) ? 0 : 32;
        const int dB = ((w < 10) ? w : (w - 10)) * 30;

        for (int tile = 0; tile < NTILE; ++tile) {
            if (tile < NTILE - 1) {
                const int nb = (tile + 1) & 1;
                const float* gs = xb + (size_t)(tile + 1) * TJ * DD;
                for (int idx = t; idx < AR_BUF / 4; idx += NT)
                    cp16(sm + OFF_AR + nb * AR_BUF + idx * 4, gs + idx * 4);
                cp_commit(); cp_wait<1>();
            } else {
                cp_wait<0>();
            }
            __syncthreads();
            const float* xs = sm + OFF_AR + (tile & 1) * AR_BUF;

            // ---- B: b[i, j = wj+lane] over this warp's 30-d chunk ----
            {
                u64 acc[NC];
                #pragma unroll
                for (int i = 0; i < NC; ++i) acc[i] = 0ull;
                const float* xrow = xs + (wj + lane) * DD + dB;
                #pragma unroll
                for (int sub = 0; sub < 3; ++sub) {
                    u64 xv[5];
                    #pragma unroll
                    for (int p = 0; p < 5; ++p)
                        xv[p] = *(const u64*)(xrow + sub * 10 + 2 * p);
                    #pragma unroll
                    for (int i = 0; i < NC; ++i) {
                        const float* vbb = v_s + i * DD + dB + sub * 10;
                        #pragma unroll
                        for (int p = 0; p < 5; ++p)
                            fma2(acc[i], xv[p], *(const u64*)(vbb + 2 * p));
                    }
                }
                #pragma unroll
                for (int i = 0; i < NC; ++i) bp[w * 352 + lane * 11 + i] = fold2(acc[i]);
            }
            __syncthreads();

            // ---- softmax over i per j: both halves in one phase ----
            if (t < 512) {
                const int jj = t >> 4, ii = t & 15;
                #pragma unroll
                for (int half = 0; half < 2; ++half) {
                    float s;
                    if (ii < NC) {
                        s = 0.f;
                        #pragma unroll
                        for (int ww = 0; ww < 10; ++ww)
                            s += bp[(half * 10 + ww) * 352 + jj * 11 + ii];
                    } else s = -1e30f;
                    float m = s;
                    #pragma unroll
                    for (int k = 8; k > 0; k >>= 1)
                        m = fmaxf(m, __shfl_xor_sync(0xffffffffu, m, k, 16));
                    const float e = __expf(s - m);
                    float su = e;
                    #pragma unroll
                    for (int k = 8; k > 0; k >>= 1)
                        su += __shfl_xor_sync(0xffffffffu, su, k, 16);
                    if (ii < NC)
                        c2[(half * 32 + jj) * NC + ii] = splat2(e * (1.0f / su));
                }
            }
            __syncthreads();

            // ---- C: yacc[i] += c[i,j] * x[j, d0c..d0c+1] (16 j per group) ----
            if (t < 600) {
                const int j0 = jg * 16;
                #pragma unroll
                for (int jj = 0; jj < 16; ++jj) {
                    const int j = j0 + jj;
                    const u64 xv = *(const u64*)(xs + j * DD + d0c);
                    #pragma unroll
                    for (int p = 0; p < 5; ++p) {
                        const u64x2_t cc = *(const u64x2_t*)(&c2[j * NC + 2 * p]);
                        fma2(yacc[2 * p],     xv, cc.x);
                        fma2(yacc[2 * p + 1], xv, cc.y);
                    }
                }
            }
            __syncthreads();
        }

        // flush yacc -> yp (overlay on arena buf0; buf0 free after tile 6), reduce
        if (t < 600) {
            #pragma unroll
            for (int i = 0; i < NC; ++i)
                *(u64*)(yp + jg * 3000 + i * DD + d0c) = yacc[i];
        }
        __syncthreads();
        for (int idx = t; idx < NC * DD; idx += NT)
            y_s[idx] = (yp[idx] + yp[3000 + idx]) + (yp[6000 + idx] + yp[9000 + idx]);
        __syncthreads();
    }
}

extern "C" void kernel_launch(void* const* d_in, const int* in_sizes, int n_in,
                              void* d_out, int out_size)
{
    const float* x = (const float*)d_in[0];
    const float* W = (const float*)d_in[1];
    if (n_in >= 2 && in_sizes[0] < in_sizes[1]) {
        x = (const float*)d_in[1];
        W = (const float*)d_in[0];
    }
    float* out = (float*)d_out;

    static int attr_done = 0;
    if (!attr_done) {
        cudaFuncSetAttribute(caps_kernel, cudaFuncAttributeMaxDynamicSharedMemorySize,
                             SMEM_BYTES);
        attr_done = 1;
    }

    dim3 tb(32, 8);
    dim3 tg(MM / 32, (DD + 31) / 32);
    transpose_W<<<tg, tb>>>(W);
    caps_kernel<<<BB, NT, SMEM_BYTES>>>(x, W, out);
}